// round 2
// baseline (speedup 1.0000x reference)
#include <cuda_runtime.h>
#include <math.h>

#define NV      12288
#define NFEAT   128
#define NHID    64
#define NCLASS  16
#define MAXDEG  128

// ---------------- device scratch (allocation-free) ----------------
__device__ int   g_cols[(size_t)NV * MAXDEG];   // neighbor column indices per row
__device__ int   g_cnt [NV];                    // per-row neighbor count (excl. self loop)
__device__ float g_dinv[NV];                    // (deg+1)^-1/2
__device__ float g_Z1  [(size_t)NV * NHID];     // d * (x @ W1)
__device__ float g_H1  [(size_t)NV * NHID];     // layer-1 activation
__device__ float g_Z2  [(size_t)NV * NCLASS];   // d * (h1 @ W2)

// ---------------- Kernel A: stream adj once -> CSR cols + degrees ----------------
// one block per row; 128 threads; float4 coalesced reads (48KB/row)
__global__ void __launch_bounds__(128) k_extract(const float* __restrict__ adj) {
    const int row = blockIdx.x;
    const float4* rp = reinterpret_cast<const float4*>(adj + (size_t)row * NV);
    __shared__ int s_cnt;
    if (threadIdx.x == 0) s_cnt = 0;
    __syncthreads();

    int* mycols = g_cols + (size_t)row * MAXDEG;
    #pragma unroll 4
    for (int idx = threadIdx.x; idx < NV / 4; idx += 128) {
        float4 v = rp[idx];
        int base = idx << 2;
        if (v.x != 0.0f) { int p = atomicAdd(&s_cnt, 1); if (p < MAXDEG) mycols[p] = base + 0; }
        if (v.y != 0.0f) { int p = atomicAdd(&s_cnt, 1); if (p < MAXDEG) mycols[p] = base + 1; }
        if (v.z != 0.0f) { int p = atomicAdd(&s_cnt, 1); if (p < MAXDEG) mycols[p] = base + 2; }
        if (v.w != 0.0f) { int p = atomicAdd(&s_cnt, 1); if (p < MAXDEG) mycols[p] = base + 3; }
    }
    __syncthreads();
    if (threadIdx.x == 0) {
        int c = s_cnt;
        g_cnt[row]  = (c < MAXDEG) ? c : MAXDEG;
        g_dinv[row] = rsqrtf((float)c + 1.0f);   // self loop included in degree
    }
}

// ---------------- Kernel B: Z1 = dinv * (x @ W1) ----------------
// block: 256 threads = 4 rows x 64 hidden cols; W1 staged in shared (32KB)
__global__ void __launch_bounds__(256) k_xw1(const float* __restrict__ x,
                                             const float* __restrict__ W1) {
    __shared__ float sW[NFEAT * NHID];   // 32 KB
    __shared__ float sx[4][NFEAT];       // 2 KB
    const int row0 = blockIdx.x * 4;
    for (int i = threadIdx.x; i < NFEAT * NHID; i += 256) sW[i] = W1[i];
    for (int i = threadIdx.x; i < 4 * NFEAT; i += 256)
        sx[i / NFEAT][i % NFEAT] = x[(size_t)(row0 + i / NFEAT) * NFEAT + (i % NFEAT)];
    __syncthreads();

    const int r = threadIdx.x >> 6;      // 0..3
    const int k = threadIdx.x & 63;      // 0..63
    float acc = 0.0f;
    #pragma unroll
    for (int f = 0; f < NFEAT; f++) acc = fmaf(sx[r][f], sW[f * NHID + k], acc);
    const int row = row0 + r;
    g_Z1[(size_t)row * NHID + k] = acc * g_dinv[row];
}

// ---------------- Kernel C: H1 = relu(dinv * (Z1_self + sum_nbr Z1)) ----------------
// block: 256 threads = 4 rows x 64 feats; Z1 (3MB) is L2-resident after B
__global__ void __launch_bounds__(256) k_spmm1() {
    const int row = blockIdx.x * 4 + (threadIdx.x >> 6);
    const int k   = threadIdx.x & 63;
    const int cnt = g_cnt[row];
    const int* cols = g_cols + (size_t)row * MAXDEG;
    float acc = g_Z1[(size_t)row * NHID + k];   // self loop term (Z1_i = d_i*Y1_i)
    for (int e = 0; e < cnt; e++) {
        int j = cols[e];
        acc += g_Z1[(size_t)j * NHID + k];
    }
    g_H1[(size_t)row * NHID + k] = fmaxf(acc * g_dinv[row], 0.0f);
}

// ---------------- Kernel D: Z2 = dinv * (H1 @ W2) ----------------
// block: 256 threads = 16 rows x 16 classes; W2 (4KB) in shared
__global__ void __launch_bounds__(256) k_hw2(const float* __restrict__ W2) {
    __shared__ float sW[NHID * NCLASS];  // 4 KB
    __shared__ float sh[16][NHID];       // 4 KB
    const int row0 = blockIdx.x * 16;
    for (int i = threadIdx.x; i < NHID * NCLASS; i += 256) sW[i] = W2[i];
    for (int i = threadIdx.x; i < 16 * NHID; i += 256)
        sh[i / NHID][i % NHID] = g_H1[(size_t)(row0 + i / NHID) * NHID + (i % NHID)];
    __syncthreads();

    const int r = threadIdx.x >> 4;      // 0..15
    const int c = threadIdx.x & 15;      // 0..15
    float acc = 0.0f;
    #pragma unroll
    for (int f = 0; f < NHID; f++) acc = fmaf(sh[r][f], sW[f * NCLASS + c], acc);
    const int row = row0 + r;
    g_Z2[(size_t)row * NCLASS + c] = acc * g_dinv[row];
}

// ---------------- Kernel E: H2 = relu(dinv*(Z2_self + sum Z2)); out = log_softmax ----------------
// block: 128 threads = 8 rows x 16 classes; 16-lane shuffle reductions
__global__ void __launch_bounds__(128) k_spmm2_out(float* __restrict__ out) {
    const int row = blockIdx.x * 8 + (threadIdx.x >> 4);
    const int c   = threadIdx.x & 15;
    const int cnt = g_cnt[row];
    const int* cols = g_cols + (size_t)row * MAXDEG;
    float acc = g_Z2[(size_t)row * NCLASS + c];
    for (int e = 0; e < cnt; e++) {
        int j = cols[e];
        acc += g_Z2[(size_t)j * NCLASS + c];
    }
    float h = fmaxf(acc * g_dinv[row], 0.0f);

    // log_softmax over 16 lanes (xor offsets 1..8 stay inside an aligned 16-lane group)
    float m = h;
    #pragma unroll
    for (int o = 8; o >= 1; o >>= 1)
        m = fmaxf(m, __shfl_xor_sync(0xffffffffu, m, o));
    float ex = expf(h - m);
    float s = ex;
    #pragma unroll
    for (int o = 8; o >= 1; o >>= 1)
        s += __shfl_xor_sync(0xffffffffu, s, o);
    out[(size_t)row * NCLASS + c] = (h - m) - logf(s);
}

// ---------------- launch ----------------
extern "C" void kernel_launch(void* const* d_in, const int* in_sizes, int n_in,
                              void* d_out, int out_size) {
    const float *x = nullptr, *adj = nullptr, *W1 = nullptr, *W2 = nullptr;
    for (int i = 0; i < n_in; i++) {
        long s = (long)in_sizes[i];
        if      (s == (long)NV * NV)      adj = (const float*)d_in[i];
        else if (s == (long)NV * NFEAT)   x   = (const float*)d_in[i];
        else if (s == (long)NFEAT * NHID) W1  = (const float*)d_in[i];
        else if (s == (long)NHID * NCLASS)W2  = (const float*)d_in[i];
    }
    float* out = (float*)d_out;

    k_extract  <<<NV,      128>>>(adj);
    k_xw1      <<<NV / 4,  256>>>(x, W1);
    k_spmm1    <<<NV / 4,  256>>>();
    k_hw2      <<<NV / 16, 256>>>(W2);
    k_spmm2_out<<<NV / 8,  128>>>(out);
}